// round 4
// baseline (speedup 1.0000x reference)
#include <cuda_runtime.h>
#include <cstdint>

#define BB   4
#define TT   1024
#define CHN  4
#define FF   481
#define KK   48
#define PPV  16
#define FT   37          // freq tile (13 * 37 = 481 exactly)
#define NTILE 13
#define FRB  4           // frames per block
#define NTHREADS 96      // 4 frames * 24 gemm threads

// ---------- packed f32x2 helpers ----------
__device__ __forceinline__ unsigned long long pk2(float x) {
    unsigned int u = __float_as_uint(x);
    unsigned long long r;
    asm("mov.b64 %0, {%1, %2};" : "=l"(r) : "r"(u), "r"(u));
    return r;
}
__device__ __forceinline__ unsigned long long fma2(unsigned long long a,
                                                   unsigned long long b,
                                                   unsigned long long c) {
    unsigned long long d;
    asm("fma.rn.f32x2 %0, %1, %2, %3;" : "=l"(d) : "l"(a), "l"(b), "l"(c));
    return d;
}
__device__ __forceinline__ float2 u2f(unsigned long long v) {
    unsigned int lo, hi;
    asm("mov.b64 {%0, %1}, %2;" : "=r"(lo), "=r"(hi) : "l"(v));
    return make_float2(__uint_as_float(lo), __uint_as_float(hi));
}

// smem layout (floats):
//   sband : [FT][96]        (br,bi interleaved per k)     3552
//   scov  : [FRB][41][16]   hermitian-compressed          2624
//   sadj  : [FRB][FT][16]                                 2368
// union total 8544 floats = 34176 B; epilogue bc buffer [FRB][48][16] float2
// (6144 floats) overlays the union.
#define SU_FLOATS 8544
#define SBAND_OFF 0
#define SCOV_OFF  (FT*96)
#define SADJ_OFF  (SCOV_OFF + FRB*41*16)

__global__ void __launch_bounds__(NTHREADS)
frame_kernel(const float* __restrict__ binr, const float* __restrict__ bini,
             const float* __restrict__ bandr, const float* __restrict__ bandi,
             const float* __restrict__ c2r,  const float* __restrict__ c2i,
             float* __restrict__ out)
{
    __shared__ __align__(16) float su[SU_FLOATS];
    __shared__ float sC[512];           // [0..255]=Cr[p][c], [256..511]=Ci[p][c]

    const int tid = threadIdx.x;
    const int g0  = blockIdx.x * FRB;   // first global frame of this block

    for (int i = tid; i < 512; i += NTHREADS)
        sC[i] = (i < 256) ? c2r[i] : c2i[i - 256];

    // GEMM thread coordinates: 4 frames x 12 kgroups x 2 c-halves
    const int fr_g = tid / 24;
    const int rr   = tid % 24;
    const int kg   = rr >> 1;           // 0..11 ; thread's k = kg + 12*j
    const int cu   = rr & 1;            // 0: pairs 01,02,03,12 ; 1: pairs 13,23 + diag

    // acc[j][kk]: j indexes 8 packed adj scalars, kk indexes 4 k's.
    // low half accumulates against br, high half against bi.
    unsigned long long acc[8][4];
#pragma unroll
    for (int j = 0; j < 8; j++)
#pragma unroll
        for (int m = 0; m < 4; m++) acc[j][m] = 0ull;

    float* sband = su + SBAND_OFF;
    float* scov  = su + SCOV_OFF;
    float* sadj  = su + SADJ_OFF;

    for (int tile = 0; tile < NTILE; tile++) {
        const int ft0 = tile * FT;
        __syncthreads();   // previous GEMM done reading su before overwrite

        // ---- stage band tile ----
        for (int i = tid; i < FT * KK; i += NTHREADS) {
            int ff = i / KK, k = i % KK;
            int f = ft0 + ff;
            sband[ff * 96 + 2 * k]     = bandr[f * KK + k];
            sband[ff * 96 + 2 * k + 1] = bandi[f * KK + k];
        }

        // ---- covariance columns (with +-2 halo, clamped) ----
        for (int i = tid; i < FRB * 41; i += NTHREADS) {
            int fr = i / 41, fe = i % 41;
            int f = ft0 - 2 + fe;
            f = f < 0 ? 0 : (f > FF - 1 ? FF - 1 : f);
            const int g = g0 + fr;
            const float* xr = binr + (size_t)g * CHN * FF + f;
            const float* xi = bini + (size_t)g * CHN * FF + f;
            float ar[4], ai[4];
#pragma unroll
            for (int c = 0; c < 4; c++) { ar[c] = xr[c * FF]; ai[c] = xi[c * FF]; }
            float pw = 0.f;
#pragma unroll
            for (int c = 0; c < 4; c++) pw += ar[c] * ar[c] + ai[c] * ai[c];
            float inv = 1.0f / fmaxf(pw, 1e-20f);
            float* dst = scov + (fr * 41 + fe) * 16;
            // pairs (i<j): cov[i,j] = x_i * conj(x_j)
            int w = 0;
#pragma unroll
            for (int a = 0; a < 4; a++)
#pragma unroll
                for (int b = a + 1; b < 4; b++) {
                    dst[w++] = (ar[a] * ar[b] + ai[a] * ai[b]) * inv;
                    dst[w++] = (ai[a] * ar[b] - ar[a] * ai[b]) * inv;
                }
#pragma unroll
            for (int c = 0; c < 4; c++)
                dst[12 + c] = (ar[c] * ar[c] + ai[c] * ai[c]) * inv;
        }
        __syncthreads();

        // ---- phase-adjusted adj (pairs: p,q ; diag: copy) ----
        for (int i = tid; i < FRB * FT; i += NTHREADS) {
            int fr = i / FT, ff = i % FT;
            int f = ft0 + ff;
            int fl = (f == 0) ? 0 : ((f == FF - 1) ? FF - 3 : f - 1);
            int fh = (f == 0) ? 2 : ((f == FF - 1) ? FF - 1 : f + 1);
            const float* c0 = scov + (fr * 41 + (ff + 2)) * 16;
            const float* cl = scov + (fr * 41 + (fl - ft0 + 2)) * 16;
            const float* ch = scov + (fr * 41 + (fh - ft0 + 2)) * 16;
            float* dst = sadj + (fr * FT + ff) * 16;
#pragma unroll
            for (int t2 = 0; t2 < 6; t2++) {
                float r0 = c0[2 * t2], i0 = c0[2 * t2 + 1];
                float rl = cl[2 * t2], il = cl[2 * t2 + 1];
                float rh = ch[2 * t2], ih = ch[2 * t2 + 1];
                float zr = rl * rh + il * ih;          // conj(cov_l)*cov_h
                float zi = rl * ih - il * rh;
                float mag = sqrtf(r0 * r0 + i0 * i0);
                float zn = rsqrtf(fmaxf(zr * zr + zi * zi, 1e-38f));
                dst[2 * t2]     = mag * zr * zn;       // p
                dst[2 * t2 + 1] = mag * zi * zn;       // q
            }
#pragma unroll
            for (int c = 0; c < 4; c++) dst[12 + c] = c0[12 + c];
        }
        __syncthreads();

        // ---- GEMM over this tile ----
        const float* adjp = sadj + fr_g * FT * 16 + cu * 8;
        const float* bnp  = sband + 2 * kg;
#pragma unroll 2
        for (int ff = 0; ff < FT; ff++) {
            float4 a0 = *reinterpret_cast<const float4*>(adjp + ff * 16);
            float4 a1 = *reinterpret_cast<const float4*>(adjp + ff * 16 + 4);
            unsigned long long b0 = *reinterpret_cast<const unsigned long long*>(bnp + ff * 96);
            unsigned long long b1 = *reinterpret_cast<const unsigned long long*>(bnp + ff * 96 + 24);
            unsigned long long b2 = *reinterpret_cast<const unsigned long long*>(bnp + ff * 96 + 48);
            unsigned long long b3 = *reinterpret_cast<const unsigned long long*>(bnp + ff * 96 + 72);
            unsigned long long v[8];
            v[0] = pk2(a0.x); v[1] = pk2(a0.y); v[2] = pk2(a0.z); v[3] = pk2(a0.w);
            v[4] = pk2(a1.x); v[5] = pk2(a1.y); v[6] = pk2(a1.z); v[7] = pk2(a1.w);
#pragma unroll
            for (int j = 0; j < 8; j++) {
                acc[j][0] = fma2(v[j], b0, acc[j][0]);
                acc[j][1] = fma2(v[j], b1, acc[j][1]);
                acc[j][2] = fma2(v[j], b2, acc[j][2]);
                acc[j][3] = fma2(v[j], b3, acc[j][3]);
            }
        }
    }

    // ---- epilogue: reconstruct bc, normalize, project ----
    __syncthreads();
    float2* bcb = reinterpret_cast<float2*>(su);   // [FRB][48][16]

#pragma unroll
    for (int m = 0; m < 4; m++) {
        int k = kg + 12 * m;
        float2* row = bcb + (fr_g * KK + k) * 16;
        if (cu == 0) {
            const int pi[4] = {0, 0, 0, 1};
            const int pj[4] = {1, 2, 3, 2};
#pragma unroll
            for (int t2 = 0; t2 < 4; t2++) {
                float2 s13 = u2f(acc[2 * t2][m]);       // (S1=Σp·br, S3=Σp·bi)
                float2 s42 = u2f(acc[2 * t2 + 1][m]);   // (S4=Σq·br, S2=Σq·bi)
                row[pi[t2] * 4 + pj[t2]] = make_float2(s13.x - s42.y, s13.y + s42.x);
                row[pj[t2] * 4 + pi[t2]] = make_float2(s13.x + s42.y, s13.y - s42.x);
            }
        } else {
            const int pi[2] = {1, 2};
            const int pj[2] = {3, 3};
#pragma unroll
            for (int t2 = 0; t2 < 2; t2++) {
                float2 s13 = u2f(acc[2 * t2][m]);
                float2 s42 = u2f(acc[2 * t2 + 1][m]);
                row[pi[t2] * 4 + pj[t2]] = make_float2(s13.x - s42.y, s13.y + s42.x);
                row[pj[t2] * 4 + pi[t2]] = make_float2(s13.x + s42.y, s13.y - s42.x);
            }
#pragma unroll
            for (int d = 0; d < 4; d++)
                row[d * 5] = u2f(acc[4 + d][m]);        // (Σd·br, Σd·bi)
        }
    }
    __syncthreads();

    for (int s = tid; s < FRB * KK; s += NTHREADS) {
        int fr = s / KK, k = s % KK;
        const float2* row = bcb + (fr * KK + k) * 16;
        float re[16], im[16];
#pragma unroll
        for (int c = 0; c < 16; c++) { float2 v = row[c]; re[c] = v.x; im[c] = v.y; }
        float ds = re[0] + re[5] + re[10] + re[15];
        float inv = 1.0f / fmaxf(ds, 1e-20f);
        int g = g0 + fr;
        int b = g >> 10, t = g & 1023;
        float* op = out + (((size_t)(b * KK + k)) * TT + t) * PPV;
#pragma unroll
        for (int p = 0; p < 16; p++) {
            float a = 0.f;
#pragma unroll
            for (int c = 0; c < 16; c++)
                a += sC[p * 16 + c] * re[c] - sC[256 + p * 16 + c] * im[c];
            op[p] = a * inv;
        }
    }
}

// ---- in-place IIR over frames: y_t = a*y_{t-1} + (1-a)*x_t, y_0 = x_0 ----
__global__ void iir_kernel(float* __restrict__ out, const float* __restrict__ tau)
{
    int idx = blockIdx.x * blockDim.x + threadIdx.x;   // (b*K+k)*16 + p
    if (idx >= BB * KK * PPV) return;
    int p  = idx & 15;
    int bk = idx >> 4;
    int k  = bk % KK;
    float a = expf(-10.0f / tau[k]);
    float bcoef = 1.0f - a;
    float* base = out + (size_t)bk * (TT * PPV) + p;
    float y = base[0];
    for (int t0 = 1; t0 < TT; t0 += 8) {
        float x[8];
#pragma unroll
        for (int u = 0; u < 8; u++) {
            int t = t0 + u;
            x[u] = (t < TT) ? base[t * PPV] : 0.f;
        }
#pragma unroll
        for (int u = 0; u < 8; u++) {
            int t = t0 + u;
            if (t < TT) { y = fmaf(a, y, bcoef * x[u]); base[t * PPV] = y; }
        }
    }
}

extern "C" void kernel_launch(void* const* d_in, const int* in_sizes, int n_in,
                              void* d_out, int out_size)
{
    const float* binr  = (const float*)d_in[0];
    const float* bini  = (const float*)d_in[1];
    const float* bandr = (const float*)d_in[2];
    const float* bandi = (const float*)d_in[3];
    const float* c2r   = (const float*)d_in[4];
    const float* c2i   = (const float*)d_in[5];
    const float* tau   = (const float*)d_in[6];
    float* out = (float*)d_out;

    frame_kernel<<<(BB * TT) / FRB, NTHREADS>>>(binr, bini, bandr, bandi, c2r, c2i, out);
    iir_kernel<<<(BB * KK * PPV + 255) / 256, 256>>>(out, tau);
}

// round 6
// speedup vs baseline: 1.1009x; 1.1009x over previous
#include <cuda_runtime.h>
#include <cstdint>

#define BB   4
#define TT   1024
#define CHN  4
#define FF   481
#define KK   48
#define PPV  16
#define FT   37          // freq tile (13 * 37 = 481 exactly)
#define NTILE 13
#define FRB  4           // frames per block
#define NTHREADS 128     // 4 frames * 32 gemm threads (1 warp per frame)

// ---------- packed f32x2 helpers ----------
__device__ __forceinline__ unsigned long long fma2(unsigned long long a,
                                                   unsigned long long b,
                                                   unsigned long long c) {
    unsigned long long d;
    asm("fma.rn.f32x2 %0, %1, %2, %3;" : "=l"(d) : "l"(a), "l"(b), "l"(c));
    return d;
}
__device__ __forceinline__ float2 u2f(unsigned long long v) {
    unsigned int lo, hi;
    asm("mov.b64 {%0, %1}, %2;" : "=r"(lo), "=r"(hi) : "l"(v));
    return make_float2(__uint_as_float(lo), __uint_as_float(hi));
}

// smem layout (floats):
//   sband : [FT][96]        (br,bi interleaved per k)        3552
//   scov  : [FRB][41][16]   hermitian-compressed             2624
//   sadj  : [FRB][FT][32]   every scalar DUPLICATED (p,p,q,q,...,d,d)  4736
// union total 10912 floats = 43648 B; epilogue bc buffer [FRB][48][16] float2
// (6144 floats) overlays the union.
#define SU_FLOATS 10912
#define SBAND_OFF 0
#define SCOV_OFF  (FT*96)
#define SADJ_OFF  (SCOV_OFF + FRB*41*16)

__global__ void __launch_bounds__(NTHREADS)
frame_kernel(const float* __restrict__ binr, const float* __restrict__ bini,
             const float* __restrict__ bandr, const float* __restrict__ bandi,
             const float* __restrict__ c2r,  const float* __restrict__ c2i,
             float* __restrict__ out)
{
    __shared__ __align__(16) float su[SU_FLOATS];
    __shared__ float sC[512];           // [0..255]=Cr[p][c], [256..511]=Ci[p][c]

    const int tid = threadIdx.x;
    const int g0  = blockIdx.x * FRB;   // first global frame of this block

    for (int i = tid; i < 512; i += NTHREADS)
        sC[i] = (i < 256) ? c2r[i] : c2i[i - 256];

    // GEMM thread coordinates: warp = frame; lanes = 16 kgroups x 2 c-halves
    const int fr_g = tid >> 5;
    const int rr   = tid & 31;
    const int kg   = rr & 15;           // 0..15 ; thread's k = kg + 16*m, m<3
    const int cu   = rr >> 4;           // 0: pairs 01,02,03,12 ; 1: pairs 13,23 + diag

    // acc[j][m]: j indexes 8 packed adj scalars, m indexes 3 k's.
    // low half accumulates against br, high half against bi.
    unsigned long long acc[8][3];
#pragma unroll
    for (int j = 0; j < 8; j++)
#pragma unroll
        for (int m = 0; m < 3; m++) acc[j][m] = 0ull;

    float* sband = su + SBAND_OFF;
    float* scov  = su + SCOV_OFF;
    float* sadj  = su + SADJ_OFF;

    for (int tile = 0; tile < NTILE; tile++) {
        const int ft0 = tile * FT;
        __syncthreads();   // previous GEMM done reading su before overwrite

        // ---- stage band tile ----
        for (int i = tid; i < FT * KK; i += NTHREADS) {
            int ff = i / KK, k = i % KK;
            int f = ft0 + ff;
            sband[ff * 96 + 2 * k]     = bandr[f * KK + k];
            sband[ff * 96 + 2 * k + 1] = bandi[f * KK + k];
        }

        // ---- covariance columns (with +-2 halo, clamped) ----
        for (int i = tid; i < FRB * 41; i += NTHREADS) {
            int fr = i / 41, fe = i % 41;
            int f = ft0 - 2 + fe;
            f = f < 0 ? 0 : (f > FF - 1 ? FF - 1 : f);
            const int g = g0 + fr;
            const float* xr = binr + (size_t)g * CHN * FF + f;
            const float* xi = bini + (size_t)g * CHN * FF + f;
            float ar[4], ai[4];
#pragma unroll
            for (int c = 0; c < 4; c++) { ar[c] = xr[c * FF]; ai[c] = xi[c * FF]; }
            float pw = 0.f;
#pragma unroll
            for (int c = 0; c < 4; c++) pw += ar[c] * ar[c] + ai[c] * ai[c];
            float inv = 1.0f / fmaxf(pw, 1e-20f);
            float* dst = scov + (fr * 41 + fe) * 16;
            int w = 0;
#pragma unroll
            for (int a = 0; a < 4; a++)
#pragma unroll
                for (int b = a + 1; b < 4; b++) {
                    dst[w++] = (ar[a] * ar[b] + ai[a] * ai[b]) * inv;
                    dst[w++] = (ai[a] * ar[b] - ar[a] * ai[b]) * inv;
                }
#pragma unroll
            for (int c = 0; c < 4; c++)
                dst[12 + c] = (ar[c] * ar[c] + ai[c] * ai[c]) * inv;
        }
        __syncthreads();

        // ---- phase-adjusted adj, written DUPLICATED: [p,p,q,q]x6 + [d,d]x4 ----
        for (int i = tid; i < FRB * FT; i += NTHREADS) {
            int fr = i / FT, ff = i % FT;
            int f = ft0 + ff;
            int fl = (f == 0) ? 0 : ((f == FF - 1) ? FF - 3 : f - 1);
            int fh = (f == 0) ? 2 : ((f == FF - 1) ? FF - 1 : f + 1);
            const float* c0 = scov + (fr * 41 + (ff + 2)) * 16;
            const float* cl = scov + (fr * 41 + (fl - ft0 + 2)) * 16;
            const float* ch = scov + (fr * 41 + (fh - ft0 + 2)) * 16;
            float* dst = sadj + (fr * FT + ff) * 32;
#pragma unroll
            for (int t2 = 0; t2 < 6; t2++) {
                float r0 = c0[2 * t2], i0 = c0[2 * t2 + 1];
                float rl = cl[2 * t2], il = cl[2 * t2 + 1];
                float rh = ch[2 * t2], ih = ch[2 * t2 + 1];
                float zr = rl * rh + il * ih;          // conj(cov_l)*cov_h
                float zi = rl * ih - il * rh;
                float mag = sqrtf(r0 * r0 + i0 * i0);
                float zn = rsqrtf(fmaxf(zr * zr + zi * zi, 1e-38f));
                float p = mag * zr * zn;
                float q = mag * zi * zn;
                dst[4 * t2 + 0] = p; dst[4 * t2 + 1] = p;
                dst[4 * t2 + 2] = q; dst[4 * t2 + 3] = q;
            }
#pragma unroll
            for (int c = 0; c < 4; c++) {
                float d = c0[12 + c];
                dst[24 + 2 * c] = d; dst[24 + 2 * c + 1] = d;
            }
        }
        __syncthreads();

        // ---- GEMM over this tile: packed operand loaded directly (no pk2) ----
        const float* adjp = sadj + fr_g * FT * 32 + cu * 16;
        const float* bnp  = sband + 2 * kg;
#pragma unroll 2
        for (int ff = 0; ff < FT; ff++) {
            const unsigned long long* vp =
                reinterpret_cast<const unsigned long long*>(adjp + ff * 32);
            unsigned long long v[8];
#pragma unroll
            for (int j = 0; j < 8; j++) v[j] = vp[j];
            unsigned long long b0 = *reinterpret_cast<const unsigned long long*>(bnp + ff * 96);
            unsigned long long b1 = *reinterpret_cast<const unsigned long long*>(bnp + ff * 96 + 32);
            unsigned long long b2 = *reinterpret_cast<const unsigned long long*>(bnp + ff * 96 + 64);
#pragma unroll
            for (int j = 0; j < 8; j++) {
                acc[j][0] = fma2(v[j], b0, acc[j][0]);
                acc[j][1] = fma2(v[j], b1, acc[j][1]);
                acc[j][2] = fma2(v[j], b2, acc[j][2]);
            }
        }
    }

    // ---- epilogue: reconstruct bc, normalize, project ----
    __syncthreads();
    float2* bcb = reinterpret_cast<float2*>(su);   // [FRB][48][16]

#pragma unroll
    for (int m = 0; m < 3; m++) {
        int k = kg + 16 * m;
        float2* row = bcb + (fr_g * KK + k) * 16;
        if (cu == 0) {
            const int pi[4] = {0, 0, 0, 1};
            const int pj[4] = {1, 2, 3, 2};
#pragma unroll
            for (int t2 = 0; t2 < 4; t2++) {
                float2 s13 = u2f(acc[2 * t2][m]);       // (S1=Σp·br, S3=Σp·bi)
                float2 s42 = u2f(acc[2 * t2 + 1][m]);   // (S4=Σq·br, S2=Σq·bi)
                row[pi[t2] * 4 + pj[t2]] = make_float2(s13.x - s42.y, s13.y + s42.x);
                row[pj[t2] * 4 + pi[t2]] = make_float2(s13.x + s42.y, s13.y - s42.x);
            }
        } else {
            const int pi[2] = {1, 2};
            const int pj[2] = {3, 3};
#pragma unroll
            for (int t2 = 0; t2 < 2; t2++) {
                float2 s13 = u2f(acc[2 * t2][m]);
                float2 s42 = u2f(acc[2 * t2 + 1][m]);
                row[pi[t2] * 4 + pj[t2]] = make_float2(s13.x - s42.y, s13.y + s42.x);
                row[pj[t2] * 4 + pi[t2]] = make_float2(s13.x + s42.y, s13.y - s42.x);
            }
#pragma unroll
            for (int d = 0; d < 4; d++)
                row[d * 5] = u2f(acc[4 + d][m]);        // (Σd·br, Σd·bi)
        }
    }
    __syncthreads();

    for (int s = tid; s < FRB * KK; s += NTHREADS) {
        int fr = s / KK, k = s % KK;
        const float2* row = bcb + (fr * KK + k) * 16;
        float re[16], im[16];
#pragma unroll
        for (int c = 0; c < 16; c++) { float2 v = row[c]; re[c] = v.x; im[c] = v.y; }
        float ds = re[0] + re[5] + re[10] + re[15];
        float inv = 1.0f / fmaxf(ds, 1e-20f);
        int g = g0 + fr;
        int b = g >> 10, t = g & 1023;
        float* op = out + (((size_t)(b * KK + k)) * TT + t) * PPV;
#pragma unroll
        for (int p = 0; p < 16; p++) {
            float a = 0.f;
#pragma unroll
            for (int c = 0; c < 16; c++)
                a += sC[p * 16 + c] * re[c] - sC[256 + p * 16 + c] * im[c];
            op[p] = a * inv;
        }
    }
}

// ---- IIR over frames as a chunked parallel scan ----
// y_t = a*y_{t-1} + (1-a)*x_t, y_0 = x_0.  Linearity: with chunk length L=32,
// true chunk-end value Y_c = local_c(zero-init) + a^L * Y_{c-1}.
// One block per (b,k): 512 threads = 16 p * 32 chunks; x held in registers.
#define IIR_L 32
__global__ void __launch_bounds__(512)
iir_kernel(float* __restrict__ out, const float* __restrict__ tau)
{
    __shared__ float zend[IIR_L * PPV];
    __shared__ float carry[IIR_L * PPV];
    const int bk  = blockIdx.x;          // b*KK + k
    const int k   = bk % KK;
    const int tid = threadIdx.x;
    const int p   = tid & 15;
    const int c   = tid >> 4;            // chunk 0..31

    float a = expf(-10.0f / tau[k]);
    float bcoef = 1.0f - a;
    // a^32 by repeated squaring
    float a2 = a * a, a4 = a2 * a2, a8 = a4 * a4, a16 = a8 * a8, pw = a16 * a16;

    float* base = out + (size_t)bk * (TT * PPV) + (size_t)c * (IIR_L * PPV) + p;

    float x[IIR_L];
#pragma unroll
    for (int i = 0; i < IIR_L; i++) x[i] = base[i * PPV];

    // local scan (chunk 0 is exact: y_0 = x_0)
    float y = (c == 0) ? x[0] : bcoef * x[0];
#pragma unroll
    for (int i = 1; i < IIR_L; i++) y = fmaf(a, y, bcoef * x[i]);
    zend[tid] = y;
    __syncthreads();

    if (tid < PPV) {
        float Y = zend[tid];             // chunk 0 end (exact)
        carry[tid] = 0.f;
#pragma unroll 4
        for (int cc = 1; cc < IIR_L; cc++) {
            carry[cc * PPV + tid] = Y;
            Y = fmaf(pw, Y, zend[cc * PPV + tid]);
        }
    }
    __syncthreads();

    float C = carry[tid];
    if (c == 0) {
        y = x[0];
        base[0] = y;
#pragma unroll
        for (int i = 1; i < IIR_L; i++) {
            y = fmaf(a, y, bcoef * x[i]);
            base[i * PPV] = y;
        }
    } else {
        y = C;
#pragma unroll
        for (int i = 0; i < IIR_L; i++) {
            y = fmaf(a, y, bcoef * x[i]);
            base[i * PPV] = y;
        }
    }
}

// No-op pad launches: make the per-replay launch count 5 so that ncu's
// "-s 5 -c 1" (launch #6 == 1 mod 5) captures frame_kernel next round.
__global__ void pad_kernel() {}

extern "C" void kernel_launch(void* const* d_in, const int* in_sizes, int n_in,
                              void* d_out, int out_size)
{
    const float* binr  = (const float*)d_in[0];
    const float* bini  = (const float*)d_in[1];
    const float* bandr = (const float*)d_in[2];
    const float* bandi = (const float*)d_in[3];
    const float* c2r   = (const float*)d_in[4];
    const float* c2i   = (const float*)d_in[5];
    const float* tau   = (const float*)d_in[6];
    float* out = (float*)d_out;

    frame_kernel<<<(BB * TT) / FRB, NTHREADS>>>(binr, bini, bandr, bandi, c2r, c2i, out);
    iir_kernel<<<BB * KK, 512>>>(out, tau);
    pad_kernel<<<1, 32>>>();
    pad_kernel<<<1, 32>>>();
    pad_kernel<<<1, 32>>>();
}

// round 9
// speedup vs baseline: 2.0346x; 1.8482x over previous
#include <cuda_runtime.h>
#include <cstdint>

#define BB   4
#define TT   1024
#define CHN  4
#define FF   481
#define KK   48
#define PPV  16
#define FT   37          // freq tile (13 * 37 = 481 exactly)
#define NTILE 13
#define FRB  4           // frames per block
#define NTHREADS 256     // 4 frames * 64 gemm threads (2 warps per frame)

// ---------- packed f32x2 helpers ----------
__device__ __forceinline__ unsigned long long fma2(unsigned long long a,
                                                   unsigned long long b,
                                                   unsigned long long c) {
    unsigned long long d;
    asm("fma.rn.f32x2 %0, %1, %2, %3;" : "=l"(d) : "l"(a), "l"(b), "l"(c));
    return d;
}
__device__ __forceinline__ float2 u2f(unsigned long long v) {
    unsigned int lo, hi;
    asm("mov.b64 {%0, %1}, %2;" : "=r"(lo), "=r"(hi) : "l"(v));
    return make_float2(__uint_as_float(lo), __uint_as_float(hi));
}
__device__ __forceinline__ unsigned long long pkpair(float lo, float hi) {
    unsigned long long r;
    asm("mov.b64 %0, {%1, %2};" : "=l"(r)
        : "r"(__float_as_uint(lo)), "r"(__float_as_uint(hi)));
    return r;
}

// smem layout (floats), strides padded for bank-conflict-free staging stores:
//   sband : [FT][96]        (br,bi interleaved per k)             3552
//   scov  : [FRB][41][18]   hermitian-compressed, pad 16->18      2952
//   sadj  : [FRB][FT][34]   duplicated scalars, pad 32->34        5032
// union total 11536 floats = 46144 B. Epilogue bc buffer overlays the
// union: [FRB*KK][17] float2 = 3264 float2 = 6528 floats.
#define COVS 18
#define ADJS 34
#define BCS  17
#define SU_FLOATS 11536
#define SBAND_OFF 0
#define SCOV_OFF  (FT*96)
#define SADJ_OFF  (SCOV_OFF + FRB*41*COVS)

__global__ void __launch_bounds__(NTHREADS, 4)
frame_kernel(const float* __restrict__ binr, const float* __restrict__ bini,
             const float* __restrict__ bandr, const float* __restrict__ bandi,
             const float* __restrict__ c2r,  const float* __restrict__ c2i,
             float* __restrict__ out)
{
    __shared__ __align__(16) float su[SU_FLOATS];
    __shared__ float sC[512];           // [0..255]=Cr[p][c], [256..511]=Ci[p][c]

    const int tid = threadIdx.x;
    const int g0  = blockIdx.x * FRB;   // first global frame of this block

    for (int i = tid; i < 512; i += NTHREADS)
        sC[i] = (i < 256) ? c2r[i] : c2i[i - 256];

    // GEMM coords: 64 threads per frame = 16 kgroups x 4 cu quarters.
    // cu0: pairs (0,1),(0,2)  cu1: (0,3),(1,2)  cu2: (1,3),(2,3)  cu3: diag
    const int fr_g = tid >> 6;
    const int tf   = tid & 63;
    const int kg   = tf & 15;           // thread's k = kg + 16*m, m<3
    const int cu   = tf >> 4;

    // acc[j][m]: j indexes 4 packed scalars of this cu, m indexes 3 k's.
    // low half accumulates against br, high half against bi.
    unsigned long long acc[4][3];
#pragma unroll
    for (int j = 0; j < 4; j++)
#pragma unroll
        for (int m = 0; m < 3; m++) acc[j][m] = 0ull;

    float* sband = su + SBAND_OFF;
    float* scov  = su + SCOV_OFF;
    float* sadj  = su + SADJ_OFF;

    for (int tile = 0; tile < NTILE; tile++) {
        const int ft0 = tile * FT;
        __syncthreads();   // previous GEMM done reading su before overwrite

        // ---- stage band tile (STS.64, consecutive addresses per lane) ----
        for (int i = tid; i < FT * KK; i += NTHREADS) {
            int ff = i / KK, k = i - ff * KK;
            int f = ft0 + ff;
            *reinterpret_cast<unsigned long long*>(sband + ff * 96 + 2 * k) =
                pkpair(bandr[f * KK + k], bandi[f * KK + k]);
        }

        // ---- covariance columns (with +-2 halo, clamped) ----
        for (int i = tid; i < FRB * 41; i += NTHREADS) {
            int fr = i / 41, fe = i - fr * 41;
            int f = ft0 - 2 + fe;
            f = f < 0 ? 0 : (f > FF - 1 ? FF - 1 : f);
            const int g = g0 + fr;
            const float* xr = binr + (size_t)g * CHN * FF + f;
            const float* xi = bini + (size_t)g * CHN * FF + f;
            float ar[4], ai[4];
#pragma unroll
            for (int c = 0; c < 4; c++) { ar[c] = xr[c * FF]; ai[c] = xi[c * FF]; }
            float pw = 0.f;
#pragma unroll
            for (int c = 0; c < 4; c++) pw += ar[c] * ar[c] + ai[c] * ai[c];
            float inv = 1.0f / fmaxf(pw, 1e-20f);
            float* dst = scov + (fr * 41 + fe) * COVS;
            int w = 0;
#pragma unroll
            for (int a = 0; a < 4; a++)
#pragma unroll
                for (int b = a + 1; b < 4; b++) {
                    dst[w++] = (ar[a] * ar[b] + ai[a] * ai[b]) * inv;
                    dst[w++] = (ai[a] * ar[b] - ar[a] * ai[b]) * inv;
                }
#pragma unroll
            for (int c = 0; c < 4; c++)
                dst[12 + c] = (ar[c] * ar[c] + ai[c] * ai[c]) * inv;
        }
        __syncthreads();

        // ---- phase-adjusted adj, DUPLICATED: [p,p,q,q]x6 + [d,d]x4 ----
        for (int i = tid; i < FRB * FT; i += NTHREADS) {
            int fr = i / FT, ff = i - fr * FT;
            int f = ft0 + ff;
            int fl = (f == 0) ? 0 : ((f == FF - 1) ? FF - 3 : f - 1);
            int fh = (f == 0) ? 2 : ((f == FF - 1) ? FF - 1 : f + 1);
            const float* c0 = scov + (fr * 41 + (ff + 2)) * COVS;
            const float* cl = scov + (fr * 41 + (fl - ft0 + 2)) * COVS;
            const float* ch = scov + (fr * 41 + (fh - ft0 + 2)) * COVS;
            float* dst = sadj + (fr * FT + ff) * ADJS;
#pragma unroll
            for (int t2 = 0; t2 < 6; t2++) {
                float r0 = c0[2 * t2], i0 = c0[2 * t2 + 1];
                float rl = cl[2 * t2], il = cl[2 * t2 + 1];
                float rh = ch[2 * t2], ih = ch[2 * t2 + 1];
                float zr = rl * rh + il * ih;          // conj(cov_l)*cov_h
                float zi = rl * ih - il * rh;
                float mag = sqrtf(r0 * r0 + i0 * i0);
                float zn = rsqrtf(fmaxf(zr * zr + zi * zi, 1e-38f));
                float p = mag * zr * zn;
                float q = mag * zi * zn;
                dst[4 * t2 + 0] = p; dst[4 * t2 + 1] = p;
                dst[4 * t2 + 2] = q; dst[4 * t2 + 3] = q;
            }
#pragma unroll
            for (int c = 0; c < 4; c++) {
                float d = c0[12 + c];
                dst[24 + 2 * c] = d; dst[24 + 2 * c + 1] = d;
            }
        }
        __syncthreads();

        // ---- GEMM over this tile: 4 broadcast v-loads + 3 b-loads + 12 FMA2 ----
        const float* adjp = sadj + fr_g * FT * ADJS + cu * 8;
        const float* bnp  = sband + 2 * kg;
        for (int ff = 0; ff < FT; ff++) {
            const unsigned long long* vp =
                reinterpret_cast<const unsigned long long*>(adjp + ff * ADJS);
            unsigned long long v0 = vp[0], v1 = vp[1], v2 = vp[2], v3 = vp[3];
            unsigned long long b0 = *reinterpret_cast<const unsigned long long*>(bnp + ff * 96);
            unsigned long long b1 = *reinterpret_cast<const unsigned long long*>(bnp + ff * 96 + 32);
            unsigned long long b2 = *reinterpret_cast<const unsigned long long*>(bnp + ff * 96 + 64);
            acc[0][0] = fma2(v0, b0, acc[0][0]);
            acc[0][1] = fma2(v0, b1, acc[0][1]);
            acc[0][2] = fma2(v0, b2, acc[0][2]);
            acc[1][0] = fma2(v1, b0, acc[1][0]);
            acc[1][1] = fma2(v1, b1, acc[1][1]);
            acc[1][2] = fma2(v1, b2, acc[1][2]);
            acc[2][0] = fma2(v2, b0, acc[2][0]);
            acc[2][1] = fma2(v2, b1, acc[2][1]);
            acc[2][2] = fma2(v2, b2, acc[2][2]);
            acc[3][0] = fma2(v3, b0, acc[3][0]);
            acc[3][1] = fma2(v3, b1, acc[3][1]);
            acc[3][2] = fma2(v3, b2, acc[3][2]);
        }
    }

    // ---- epilogue: reconstruct bc, normalize, project ----
    __syncthreads();
    float2* bcb = reinterpret_cast<float2*>(su);   // [FRB*KK][BCS]

    {
        const int pi[6] = {0, 0, 0, 1, 1, 2};
        const int pj[6] = {1, 2, 3, 2, 3, 3};
#pragma unroll
        for (int m = 0; m < 3; m++) {
            int k = kg + 16 * m;
            float2* row = bcb + (fr_g * KK + k) * BCS;
            if (cu < 3) {
#pragma unroll
                for (int t2l = 0; t2l < 2; t2l++) {
                    int t2 = cu * 2 + t2l;
                    float2 s13 = u2f(acc[2 * t2l][m]);       // (Σp·br, Σp·bi)
                    float2 s42 = u2f(acc[2 * t2l + 1][m]);   // (Σq·br, Σq·bi)
                    row[pi[t2] * 4 + pj[t2]] = make_float2(s13.x - s42.y, s13.y + s42.x);
                    row[pj[t2] * 4 + pi[t2]] = make_float2(s13.x + s42.y, s13.y - s42.x);
                }
            } else {
#pragma unroll
                for (int d = 0; d < 4; d++)
                    row[d * 5] = u2f(acc[d][m]);             // (Σd·br, Σd·bi)
            }
        }
    }
    __syncthreads();

    for (int s = tid; s < FRB * KK; s += NTHREADS) {
        int fr = s / KK, k = s - fr * KK;
        const float2* row = bcb + (fr * KK + k) * BCS;
        float re[16], im[16];
#pragma unroll
        for (int c = 0; c < 16; c++) { float2 v = row[c]; re[c] = v.x; im[c] = v.y; }
        float ds = re[0] + re[5] + re[10] + re[15];
        float inv = 1.0f / fmaxf(ds, 1e-20f);
        int g = g0 + fr;
        int b = g >> 10, t = g & 1023;
        float* op = out + (((size_t)(b * KK + k)) * TT + t) * PPV;
#pragma unroll
        for (int p = 0; p < 16; p++) {
            float a = 0.f;
#pragma unroll
            for (int c = 0; c < 16; c++)
                a += sC[p * 16 + c] * re[c] - sC[256 + p * 16 + c] * im[c];
            op[p] = a * inv;
        }
    }
}

// ---- IIR over frames as a chunked parallel scan ----
// y_t = a*y_{t-1} + (1-a)*x_t, y_0 = x_0.  Linearity: with chunk length L=32,
// true chunk-end value Y_c = local_c(zero-init) + a^L * Y_{c-1}.
// One block per (b,k): 512 threads = 16 p * 32 chunks; x held in registers.
#define IIR_L 32
__global__ void __launch_bounds__(512)
iir_kernel(float* __restrict__ out, const float* __restrict__ tau)
{
    __shared__ float zend[IIR_L * PPV];
    __shared__ float carry[IIR_L * PPV];
    const int bk  = blockIdx.x;          // b*KK + k
    const int k   = bk % KK;
    const int tid = threadIdx.x;
    const int p   = tid & 15;
    const int c   = tid >> 4;            // chunk 0..31

    float a = expf(-10.0f / tau[k]);
    float bcoef = 1.0f - a;
    float a2 = a * a, a4 = a2 * a2, a8 = a4 * a4, a16 = a8 * a8, pw = a16 * a16;

    float* base = out + (size_t)bk * (TT * PPV) + (size_t)c * (IIR_L * PPV) + p;

    float x[IIR_L];
#pragma unroll
    for (int i = 0; i < IIR_L; i++) x[i] = base[i * PPV];

    float y = (c == 0) ? x[0] : bcoef * x[0];
#pragma unroll
    for (int i = 1; i < IIR_L; i++) y = fmaf(a, y, bcoef * x[i]);
    zend[tid] = y;
    __syncthreads();

    if (tid < PPV) {
        float Y = zend[tid];             // chunk 0 end (exact)
        carry[tid] = 0.f;
#pragma unroll 4
        for (int cc = 1; cc < IIR_L; cc++) {
            carry[cc * PPV + tid] = Y;
            Y = fmaf(pw, Y, zend[cc * PPV + tid]);
        }
    }
    __syncthreads();

    float C = carry[tid];
    if (c == 0) {
        y = x[0];
        base[0] = y;
#pragma unroll
        for (int i = 1; i < IIR_L; i++) {
            y = fmaf(a, y, bcoef * x[i]);
            base[i * PPV] = y;
        }
    } else {
        y = C;
#pragma unroll
        for (int i = 0; i < IIR_L; i++) {
            y = fmaf(a, y, bcoef * x[i]);
            base[i * PPV] = y;
        }
    }
}

extern "C" void kernel_launch(void* const* d_in, const int* in_sizes, int n_in,
                              void* d_out, int out_size)
{
    const float* binr  = (const float*)d_in[0];
    const float* bini  = (const float*)d_in[1];
    const float* bandr = (const float*)d_in[2];
    const float* bandi = (const float*)d_in[3];
    const float* c2r   = (const float*)d_in[4];
    const float* c2i   = (const float*)d_in[5];
    const float* tau   = (const float*)d_in[6];
    float* out = (float*)d_out;

    frame_kernel<<<(BB * TT) / FRB, NTHREADS>>>(binr, bini, bandr, bandi, c2r, c2i, out);
    iir_kernel<<<BB * KK, 512>>>(out, tau);
}